// round 1
// baseline (speedup 1.0000x reference)
#include <cuda_runtime.h>
#include <cuda_bf16.h>

#define NS   8192
#define DIM  128
#define NC   1024
#define MARGIN 0.3f

// ---------------- scratch (device globals; no allocation allowed) -----------
__device__ float    g_M[NC * DIM];     // class means
__device__ float    g_cm2[NC];         // ||mean||^2
__device__ int      g_count[NC];       // class counts
__device__ float    g_x2[NS];          // row squared norms
__device__ unsigned g_pos[NC];         // encoded max positive dist2 per class
__device__ unsigned g_neg[NC];         // encoded min negative dist2 per class

// order-preserving float <-> uint encoding (monotone for all finite floats)
__device__ __forceinline__ unsigned encf(float f) {
    unsigned u = __float_as_uint(f);
    return (u & 0x80000000u) ? ~u : (u | 0x80000000u);
}
__device__ __forceinline__ float decf(unsigned e) {
    return (e & 0x80000000u) ? __uint_as_float(e ^ 0x80000000u)
                             : __uint_as_float(~e);
}

// ---------------- K0: init ---------------------------------------------------
__global__ void k_init() {
    int c = blockIdx.x * blockDim.x + threadIdx.x;
    if (c < NC) {
        g_count[c] = 0;
        g_pos[c]   = 0u;           // enc(-inf) < this never matters; 0 = minimum
        g_neg[c]   = 0xFFFFFFFFu;  // maximum
    }
}

// ---------------- K1: row norms + class counts (one warp per row) ------------
__global__ void k_rownorm(const float* __restrict__ X, const int* __restrict__ T) {
    int gw   = (blockIdx.x * blockDim.x + threadIdx.x) >> 5;
    int lane = threadIdx.x & 31;
    if (gw >= NS) return;
    const float4* row = reinterpret_cast<const float4*>(X + (size_t)gw * DIM);
    float4 v = row[lane];
    float s = v.x * v.x + v.y * v.y + v.z * v.z + v.w * v.w;
    #pragma unroll
    for (int o = 16; o; o >>= 1) s += __shfl_xor_sync(0xffffffffu, s, o);
    if (lane == 0) {
        g_x2[gw] = s;
        atomicAdd(&g_count[T[gw]], 1);   // integer atomic: deterministic
    }
}

// ---------------- K2: class means + ||mean||^2 (4 classes per block) ---------
// 128 threads = DIM; deterministic accumulation order (j ascending).
__global__ __launch_bounds__(128) void k_centers(const float* __restrict__ X,
                                                 const int* __restrict__ T) {
    __shared__ int   st[NS];       // 32 KB
    __shared__ float rbuf[128];
    int tid = threadIdx.x;
    for (int i = tid; i < NS; i += 128) st[i] = T[i];
    __syncthreads();

    int cb = blockIdx.x * 4;
    float s0 = 0.f, s1 = 0.f, s2 = 0.f, s3 = 0.f;

    for (int j = 0; j < NS; j += 8) {
        int t[8];
        #pragma unroll
        for (int u = 0; u < 8; u++) t[u] = st[j + u];
        bool any = false;
        #pragma unroll
        for (int u = 0; u < 8; u++) any |= ((unsigned)(t[u] - cb) < 4u);
        if (any) {
            #pragma unroll
            for (int u = 0; u < 8; u++) {
                unsigned dt = (unsigned)(t[u] - cb);
                if (dt < 4u) {
                    float v = X[(size_t)(j + u) * DIM + tid];
                    if      (dt == 0u) s0 += v;
                    else if (dt == 1u) s1 += v;
                    else if (dt == 2u) s2 += v;
                    else               s3 += v;
                }
            }
        }
    }

    float mv[4] = {s0, s1, s2, s3};
    #pragma unroll
    for (int cl = 0; cl < 4; cl++) {
        int cnt = g_count[cb + cl];
        float m = (cnt > 0) ? mv[cl] / (float)cnt : 0.f;
        g_M[(size_t)(cb + cl) * DIM + tid] = m;
        rbuf[tid] = m * m;
        __syncthreads();
        for (int o = 64; o; o >>= 1) {
            if (tid < o) rbuf[tid] += rbuf[tid + o];
            __syncthreads();
        }
        if (tid == 0) g_cm2[cb + cl] = rbuf[0];
        __syncthreads();
    }
}

// ---------------- K3: fused class-vs-sample distances + hard mining ----------
#define CB 16       // classes per block
#define JB 1024     // samples per block
#define JT 4        // samples per thread
__global__ __launch_bounds__(256) void k_main(const float* __restrict__ X,
                                              const int* __restrict__ T) {
    __shared__ float4   Ms[CB][DIM / 4];   // 8 KB, broadcast reads
    __shared__ float    cm2s[CB];
    __shared__ unsigned spos[CB], sneg[CB];

    int tid   = threadIdx.x;
    int cgrid = NC / CB;                       // 64
    int cbase = (blockIdx.x % cgrid) * CB;
    int jbase = (blockIdx.x / cgrid) * JB;

    for (int i = tid; i < CB * (DIM / 4); i += 256) {
        int c = i / (DIM / 4), d4 = i % (DIM / 4);
        Ms[c][d4] = reinterpret_cast<const float4*>(g_M)[(size_t)(cbase + c) * (DIM / 4) + d4];
    }
    if (tid < CB) {
        cm2s[tid] = g_cm2[cbase + tid];
        spos[tid] = 0u;
        sneg[tid] = 0xFFFFFFFFu;
    }
    __syncthreads();

    int j0 = jbase + tid;                      // + k*256, k<JT

    float acc[CB][JT];
    #pragma unroll
    for (int c = 0; c < CB; c++)
        #pragma unroll
        for (int k = 0; k < JT; k++) acc[c][k] = 0.f;

    const float4* Xv = reinterpret_cast<const float4*>(X);
    #pragma unroll 4
    for (int d4 = 0; d4 < DIM / 4; d4++) {
        float4 xv[JT];
        #pragma unroll
        for (int k = 0; k < JT; k++)
            xv[k] = Xv[(size_t)(j0 + k * 256) * (DIM / 4) + d4];
        #pragma unroll
        for (int c = 0; c < CB; c++) {
            float4 m = Ms[c][d4];
            #pragma unroll
            for (int k = 0; k < JT; k++)
                acc[c][k] += m.x * xv[k].x + m.y * xv[k].y
                           + m.z * xv[k].z + m.w * xv[k].w;
        }
    }

    int   tj[JT];
    float xx[JT];
    #pragma unroll
    for (int k = 0; k < JT; k++) {
        tj[k] = T[j0 + k * 256];
        xx[k] = g_x2[j0 + k * 256];
    }

    #pragma unroll
    for (int c = 0; c < CB; c++) {
        int cls = cbase + c;
        #pragma unroll
        for (int k = 0; k < JT; k++) {
            float d2  = cm2s[c] + xx[k] - 2.f * acc[c][k];
            unsigned e = encf(d2);
            bool ispos = (tj[k] == cls);
            unsigned ep = ispos ? e : 0u;
            unsigned en = ispos ? 0xFFFFFFFFu : e;
            ep = __reduce_max_sync(0xffffffffu, ep);
            en = __reduce_min_sync(0xffffffffu, en);
            if ((tid & 31) == 0) {
                atomicMax(&spos[c], ep);
                atomicMin(&sneg[c], en);
            }
        }
    }
    __syncthreads();
    if (tid < CB) {
        atomicMax(&g_pos[cbase + tid], spos[tid]);
        atomicMin(&g_neg[cbase + tid], sneg[tid]);
    }
}

// ---------------- K4: weighted final reduction -------------------------------
__global__ __launch_bounds__(1024) void k_final(float* __restrict__ out, int out_size) {
    __shared__ float sl[1024];
    __shared__ float sp[1024];
    int c = threadIdx.x;
    int cnt = g_count[c];
    float l = 0.f, p = 0.f;
    if (cnt > 0) {
        float pos = decf(g_pos[c]);
        float neg = decf(g_neg[c]);
        float d = pos - neg + MARGIN;
        l = (float)cnt * (d > 0.f ? d : 0.f);
        p = (float)cnt * (neg > pos ? 1.f : 0.f);
    }
    sl[c] = l;
    sp[c] = p;
    __syncthreads();
    for (int o = 512; o; o >>= 1) {
        if (c < o) { sl[c] += sl[c + o]; sp[c] += sp[c + o]; }
        __syncthreads();
    }
    if (c == 0) {
        out[0] = sl[0] / (float)NS;
        if (out_size > 1) out[1] = sp[0] / (float)NS;
    }
}

// ---------------- launch -----------------------------------------------------
extern "C" void kernel_launch(void* const* d_in, const int* in_sizes, int n_in,
                              void* d_out, int out_size) {
    const float* X = (const float*)d_in[0];
    const int*   T = (const int*)d_in[1];
    float*       O = (float*)d_out;

    k_init<<<NC / 256, 256>>>();
    k_rownorm<<<(NS * 32) / 256, 256>>>(X, T);
    k_centers<<<NC / 4, 128>>>(X, T);
    k_main<<<(NC / CB) * (NS / JB), 256>>>(X, T);
    k_final<<<1, 1024>>>(O, out_size);
}

// round 3
// speedup vs baseline: 1.9679x; 1.9679x over previous
#include <cuda_runtime.h>
#include <cuda_bf16.h>

#define NS   8192
#define DIM  128
#define NC   1024
#define MARGIN 0.3f
#define LISTCAP 64

typedef unsigned long long ull;

// ---------------- scratch (device globals) ----------------------------------
__device__ float    g_M[NC * DIM];       // class means
__device__ float    g_cm2[NC];           // ||mean||^2
__device__ int      g_count[NC];         // class counts
__device__ int      g_list[NC][LISTCAP]; // per-class sample indices (ordered)
__device__ float    g_x2[NS];            // row squared norms
__device__ unsigned g_pos[NC];           // encoded max positive dist2 per class
__device__ unsigned g_neg[NC];           // encoded min negative dist2 per class

// order-preserving float <-> uint encoding
__device__ __forceinline__ unsigned encf(float f) {
    unsigned u = __float_as_uint(f);
    return (u & 0x80000000u) ? ~u : (u | 0x80000000u);
}
__device__ __forceinline__ float decf(unsigned e) {
    return (e & 0x80000000u) ? __uint_as_float(e ^ 0x80000000u)
                             : __uint_as_float(~e);
}

// packed f32x2 helpers (Blackwell FFMA2 — only reachable via PTX)
__device__ __forceinline__ ull packf2(float x, float y) {
    ull r; asm("mov.b64 %0, {%1, %2};" : "=l"(r) : "f"(x), "f"(y)); return r;
}
__device__ __forceinline__ void unpackf2(float& x, float& y, ull p) {
    asm("mov.b64 {%0, %1}, %2;" : "=f"(x), "=f"(y) : "l"(p));
}
__device__ __forceinline__ ull fma2(ull a, ull b, ull c) {
    ull d; asm("fma.rn.f32x2 %0, %1, %2, %3;" : "=l"(d) : "l"(a), "l"(b), "l"(c));
    return d;
}

// ---------------- K1: per-class ordered index lists + counts + init ----------
// 32 blocks x 1024 threads; warp w of block b owns class b*32+w.
__global__ __launch_bounds__(1024) void k_index(const int* __restrict__ T) {
    __shared__ int sT[NS];   // 32 KB
    int tid = threadIdx.x;
    for (int i = tid; i < NS; i += 1024) sT[i] = T[i];
    __syncthreads();
    int w = tid >> 5, lane = tid & 31;
    int c = blockIdx.x * 32 + w;
    if (lane == 0) { g_pos[c] = 0u; g_neg[c] = 0xFFFFFFFFu; }
    int cnt = 0;
    for (int base = 0; base < NS; base += 32) {
        int t = sT[base + lane];
        unsigned bal = __ballot_sync(0xffffffffu, t == c);
        if (t == c) {
            int pos = cnt + __popc(bal & ((1u << lane) - 1u));
            if (pos < LISTCAP) g_list[c][pos] = base + lane;
        }
        cnt += __popc(bal);
    }
    if (lane == 0) g_count[c] = cnt;
}

// ---------------- K2: row squared norms (one warp per row) -------------------
__global__ void k_rownorm(const float* __restrict__ X) {
    int gw   = (blockIdx.x * blockDim.x + threadIdx.x) >> 5;
    int lane = threadIdx.x & 31;
    if (gw >= NS) return;
    const float4* row = reinterpret_cast<const float4*>(X + (size_t)gw * DIM);
    float4 v = row[lane];
    float s = v.x * v.x + v.y * v.y + v.z * v.z + v.w * v.w;
    #pragma unroll
    for (int o = 16; o; o >>= 1) s += __shfl_xor_sync(0xffffffffu, s, o);
    if (lane == 0) g_x2[gw] = s;
}

// ---------------- K3: class means via gathered lists (block per class) -------
__global__ __launch_bounds__(128) void k_centers(const float* __restrict__ X) {
    int c = blockIdx.x, tid = threadIdx.x;
    int cnt = g_count[c];
    int cl = cnt > LISTCAP ? LISTCAP : cnt;
    float s = 0.f;
    int i = 0;
    for (; i + 4 <= cl; i += 4) {
        int i0 = g_list[c][i], i1 = g_list[c][i+1], i2 = g_list[c][i+2], i3 = g_list[c][i+3];
        float v0 = X[(size_t)i0 * DIM + tid];
        float v1 = X[(size_t)i1 * DIM + tid];
        float v2 = X[(size_t)i2 * DIM + tid];
        float v3 = X[(size_t)i3 * DIM + tid];
        s += v0; s += v1; s += v2; s += v3;
    }
    for (; i < cl; i++) s += X[(size_t)g_list[c][i] * DIM + tid];
    float m = (cnt > 0) ? s / (float)cnt : 0.f;
    g_M[(size_t)c * DIM + tid] = m;
    // reduce ||m||^2 over 128 threads
    float q = m * m;
    #pragma unroll
    for (int o = 16; o; o >>= 1) q += __shfl_xor_sync(0xffffffffu, q, o);
    __shared__ float r[4];
    if ((tid & 31) == 0) r[tid >> 5] = q;
    __syncthreads();
    if (tid == 0) g_cm2[c] = r[0] + r[1] + r[2] + r[3];
}

// ---------------- K4: tiled SGEMM (FFMA2) + hard mining ----------------------
// Block tile: MT=128 classes x NT=128 samples, K=DIM=128 in 4 chunks of 32.
// 512 threads, micro-tile 8m x 4n (n strided by 32 across lanes).
// Smem K-pair-interleaved: S[k2][idx] = (val[2*k2], val[2*k2+1]).
// Row pad +2 ulls: stride 1040 B = 16-byte aligned (LDS.128 safe) AND shifts
// banks by 4 per row (staging-write conflict spread).
#define MT  128
#define NT  128
#define K2C 16
#define PAD 2
__global__ __launch_bounds__(512, 1) void k_main(const float* __restrict__ X,
                                                 const int* __restrict__ T) {
    __shared__ ull As[K2C][MT + PAD];   // 16.25 KB
    __shared__ ull Bs[K2C][NT + PAD];   // 16.25 KB

    int tid = threadIdx.x, lane = tid & 31, ty = tid >> 5;
    int cbase = (blockIdx.x & 7) * MT;
    int nbase = (blockIdx.x >> 3) * NT;

    int srow = tid >> 2, kq = tid & 3;   // staging: row + k-quad (8 floats)
    const float4* Arow = reinterpret_cast<const float4*>(g_M + (size_t)(cbase + srow) * DIM);
    const float4* Brow = reinterpret_cast<const float4*>(X   + (size_t)(nbase + srow) * DIM);

    ull acc[8][4];
    #pragma unroll
    for (int mi = 0; mi < 8; mi++)
        #pragma unroll
        for (int ni = 0; ni < 4; ni++) acc[mi][ni] = 0ull;

    // prefetch chunk 0 (float4 index within row: chunk*8 + kq*2)
    float4 av0 = Arow[kq * 2], av1 = Arow[kq * 2 + 1];
    float4 bv0 = Brow[kq * 2], bv1 = Brow[kq * 2 + 1];

    for (int chunk = 0; chunk < 4; chunk++) {
        As[kq * 4 + 0][srow] = packf2(av0.x, av0.y);
        As[kq * 4 + 1][srow] = packf2(av0.z, av0.w);
        As[kq * 4 + 2][srow] = packf2(av1.x, av1.y);
        As[kq * 4 + 3][srow] = packf2(av1.z, av1.w);
        Bs[kq * 4 + 0][srow] = packf2(bv0.x, bv0.y);
        Bs[kq * 4 + 1][srow] = packf2(bv0.z, bv0.w);
        Bs[kq * 4 + 2][srow] = packf2(bv1.x, bv1.y);
        Bs[kq * 4 + 3][srow] = packf2(bv1.z, bv1.w);
        __syncthreads();
        if (chunk < 3) {
            int o = (chunk + 1) * 8 + kq * 2;
            av0 = Arow[o]; av1 = Arow[o + 1];
            bv0 = Brow[o]; bv1 = Brow[o + 1];
        }
        #pragma unroll
        for (int k2 = 0; k2 < K2C; k2++) {
            ull a[8], b[4];
            const ulonglong2* ap = reinterpret_cast<const ulonglong2*>(&As[k2][ty * 8]);
            #pragma unroll
            for (int h = 0; h < 4; h++) {
                ulonglong2 p = ap[h];
                a[2 * h] = p.x; a[2 * h + 1] = p.y;
            }
            #pragma unroll
            for (int ni = 0; ni < 4; ni++) b[ni] = Bs[k2][lane + 32 * ni];
            #pragma unroll
            for (int mi = 0; mi < 8; mi++)
                #pragma unroll
                for (int ni = 0; ni < 4; ni++)
                    acc[mi][ni] = fma2(a[mi], b[ni], acc[mi][ni]);
        }
        __syncthreads();
    }

    // epilogue: dist2 + per-class hard mining
    float x2v[4]; int tj[4];
    #pragma unroll
    for (int ni = 0; ni < 4; ni++) {
        int n = nbase + lane + 32 * ni;
        x2v[ni] = g_x2[n];
        tj[ni]  = T[n];
    }
    #pragma unroll
    for (int mi = 0; mi < 8; mi++) {
        int m = ty * 8 + mi, cls = cbase + m;
        float c2 = g_cm2[cls];
        unsigned ep = 0u, en = 0xFFFFFFFFu;
        #pragma unroll
        for (int ni = 0; ni < 4; ni++) {
            float lo, hi; unpackf2(lo, hi, acc[mi][ni]);
            float d2 = c2 + x2v[ni] - 2.f * (lo + hi);
            unsigned e = encf(d2);
            if (tj[ni] == cls) ep = ep > e ? ep : e;
            else               en = en < e ? en : e;
        }
        ep = __reduce_max_sync(0xffffffffu, ep);
        en = __reduce_min_sync(0xffffffffu, en);
        if (lane == 0) {
            atomicMax(&g_pos[cls], ep);
            atomicMin(&g_neg[cls], en);
        }
    }
}

// ---------------- K5: weighted final reduction -------------------------------
__global__ __launch_bounds__(1024) void k_final(float* __restrict__ out, int out_size) {
    __shared__ float sl[1024];
    __shared__ float sp[1024];
    int c = threadIdx.x;
    int cnt = g_count[c];
    float l = 0.f, p = 0.f;
    if (cnt > 0) {
        float pos = decf(g_pos[c]);
        float neg = decf(g_neg[c]);
        float d = pos - neg + MARGIN;
        l = (float)cnt * (d > 0.f ? d : 0.f);
        p = (float)cnt * (neg > pos ? 1.f : 0.f);
    }
    sl[c] = l;
    sp[c] = p;
    __syncthreads();
    for (int o = 512; o; o >>= 1) {
        if (c < o) { sl[c] += sl[c + o]; sp[c] += sp[c + o]; }
        __syncthreads();
    }
    if (c == 0) {
        out[0] = sl[0] / (float)NS;
        if (out_size > 1) out[1] = sp[0] / (float)NS;
    }
}

// ---------------- launch -----------------------------------------------------
extern "C" void kernel_launch(void* const* d_in, const int* in_sizes, int n_in,
                              void* d_out, int out_size) {
    const float* X = (const float*)d_in[0];
    const int*   T = (const int*)d_in[1];
    float*       O = (float*)d_out;

    k_index<<<NC / 32, 1024>>>(T);
    k_rownorm<<<(NS * 32) / 256, 256>>>(X);
    k_centers<<<NC, 128>>>(X);
    k_main<<<(NC / MT) * (NS / NT), 512>>>(X, T);
    k_final<<<1, 1024>>>(O, out_size);
}

// round 4
// speedup vs baseline: 2.0442x; 1.0388x over previous
#include <cuda_runtime.h>
#include <cuda_bf16.h>

#define NS   8192
#define DIM  128
#define NC   1024
#define MARGIN 0.3f
#define LISTCAP 64

typedef unsigned long long ull;

// ---------------- scratch (device globals) ----------------------------------
__device__ float    g_M[NC * DIM];       // class means
__device__ float    g_cm2[NC];           // ||mean||^2
__device__ int      g_count[NC];         // class counts
__device__ int      g_list[NC][LISTCAP]; // per-class sample indices (ordered)
__device__ float    g_x2[NS];            // row squared norms
__device__ unsigned g_pos[NC];           // encoded max positive dist2 per class
__device__ unsigned g_neg[NC];           // encoded min negative dist2 per class

// order-preserving float <-> uint encoding
__device__ __forceinline__ unsigned encf(float f) {
    unsigned u = __float_as_uint(f);
    return (u & 0x80000000u) ? ~u : (u | 0x80000000u);
}
__device__ __forceinline__ float decf(unsigned e) {
    return (e & 0x80000000u) ? __uint_as_float(e ^ 0x80000000u)
                             : __uint_as_float(~e);
}

// packed f32x2 helpers (Blackwell FFMA2 — only reachable via PTX)
__device__ __forceinline__ ull packf2(float x, float y) {
    ull r; asm("mov.b64 %0, {%1, %2};" : "=l"(r) : "f"(x), "f"(y)); return r;
}
__device__ __forceinline__ void unpackf2(float& x, float& y, ull p) {
    asm("mov.b64 {%0, %1}, %2;" : "=f"(x), "=f"(y) : "l"(p));
}
__device__ __forceinline__ ull fma2(ull a, ull b, ull c) {
    ull d; asm("fma.rn.f32x2 %0, %1, %2, %3;" : "=l"(d) : "l"(a), "l"(b), "l"(c));
    return d;
}

// ---------------- K1: fused index-build + row norms --------------------------
// blocks 0..31  : per-class ordered lists + counts + mining init (warp/class)
// blocks 32..287: row squared norms (warp/row)
__global__ __launch_bounds__(1024) void k_pre(const float* __restrict__ X,
                                              const int* __restrict__ T) {
    int tid = threadIdx.x, w = tid >> 5, lane = tid & 31;
    if (blockIdx.x < 32) {
        __shared__ int sT[NS];   // 32 KB
        for (int i = tid; i < NS; i += 1024) sT[i] = T[i];
        __syncthreads();
        int c = blockIdx.x * 32 + w;
        if (lane == 0) { g_pos[c] = 0u; g_neg[c] = 0xFFFFFFFFu; }
        int cnt = 0;
        for (int base = 0; base < NS; base += 32) {
            int t = sT[base + lane];
            unsigned bal = __ballot_sync(0xffffffffu, t == c);
            if (t == c) {
                int pos = cnt + __popc(bal & ((1u << lane) - 1u));
                if (pos < LISTCAP) g_list[c][pos] = base + lane;
            }
            cnt += __popc(bal);
        }
        if (lane == 0) g_count[c] = cnt;
    } else {
        int row = (blockIdx.x - 32) * 32 + w;
        const float4* rp = reinterpret_cast<const float4*>(X + (size_t)row * DIM);
        float4 v = rp[lane];
        float s = v.x * v.x + v.y * v.y + v.z * v.z + v.w * v.w;
        #pragma unroll
        for (int o = 16; o; o >>= 1) s += __shfl_xor_sync(0xffffffffu, s, o);
        if (lane == 0) g_x2[row] = s;
    }
}

// ---------------- K2: class means via gathered lists (block per class) -------
__global__ __launch_bounds__(128) void k_centers(const float* __restrict__ X) {
    int c = blockIdx.x, tid = threadIdx.x;
    int cnt = g_count[c];
    int cl = cnt > LISTCAP ? LISTCAP : cnt;
    float s = 0.f;
    int i = 0;
    for (; i + 4 <= cl; i += 4) {
        int i0 = g_list[c][i], i1 = g_list[c][i+1], i2 = g_list[c][i+2], i3 = g_list[c][i+3];
        float v0 = X[(size_t)i0 * DIM + tid];
        float v1 = X[(size_t)i1 * DIM + tid];
        float v2 = X[(size_t)i2 * DIM + tid];
        float v3 = X[(size_t)i3 * DIM + tid];
        s += v0; s += v1; s += v2; s += v3;
    }
    for (; i < cl; i++) s += X[(size_t)g_list[c][i] * DIM + tid];
    float m = (cnt > 0) ? s / (float)cnt : 0.f;
    g_M[(size_t)c * DIM + tid] = m;
    float q = m * m;
    #pragma unroll
    for (int o = 16; o; o >>= 1) q += __shfl_xor_sync(0xffffffffu, q, o);
    __shared__ float r[4];
    if ((tid & 31) == 0) r[tid >> 5] = q;
    __syncthreads();
    if (tid == 0) g_cm2[c] = r[0] + r[1] + r[2] + r[3];
}

// ---------------- K3: tiled SGEMM (FFMA2) + hard mining ----------------------
// Block tile MT=128 classes x NT=128 samples; 512 threads = 16 warps (2m x 8n
// warp grid); warp tile 64m x 16n; lane (mg=lane>>2, ng=lane&3).
// Per-thread micro-tile 8m x 4n, all smem fragment loads are LDS.128 over
// broadcast groups (1 crossbar phase each).
// Smem K-pair-interleaved: S[k2][idx] = (val[2*k2], val[2*k2+1]); row pad +2
// ulls keeps 16-byte alignment.
#define MT  128
#define NT  128
#define K2C 16
#define PAD 2
__global__ __launch_bounds__(512, 1) void k_main(const float* __restrict__ X,
                                                 const int* __restrict__ T) {
    __shared__ ull      As[K2C][MT + PAD];   // 16.25 KB
    __shared__ ull      Bs[K2C][NT + PAD];   // 16.25 KB
    __shared__ unsigned spos[MT], sneg[MT];
    __shared__ float    scm2[MT];

    int tid = threadIdx.x, lane = tid & 31, w = tid >> 5;
    int wm = w & 1, wn = w >> 1;             // warp grid 2 x 8
    int mg = lane >> 2, ng = lane & 3;       // lane grid 8 x 4
    int cbase = (blockIdx.x & 7) * MT;
    int nbase = (blockIdx.x >> 3) * NT;

    if (tid < MT) {
        spos[tid] = 0u;
        sneg[tid] = 0xFFFFFFFFu;
        scm2[tid] = g_cm2[cbase + tid];
    }

    int srow = tid >> 2, kq = tid & 3;       // staging: row + k-quad (8 floats)
    const float4* Arow = reinterpret_cast<const float4*>(g_M + (size_t)(cbase + srow) * DIM);
    const float4* Brow = reinterpret_cast<const float4*>(X   + (size_t)(nbase + srow) * DIM);

    ull acc[8][4];
    #pragma unroll
    for (int mi = 0; mi < 8; mi++)
        #pragma unroll
        for (int ni = 0; ni < 4; ni++) acc[mi][ni] = 0ull;

    float4 av0 = Arow[kq * 2], av1 = Arow[kq * 2 + 1];
    float4 bv0 = Brow[kq * 2], bv1 = Brow[kq * 2 + 1];

    for (int chunk = 0; chunk < 4; chunk++) {
        As[kq * 4 + 0][srow] = packf2(av0.x, av0.y);
        As[kq * 4 + 1][srow] = packf2(av0.z, av0.w);
        As[kq * 4 + 2][srow] = packf2(av1.x, av1.y);
        As[kq * 4 + 3][srow] = packf2(av1.z, av1.w);
        Bs[kq * 4 + 0][srow] = packf2(bv0.x, bv0.y);
        Bs[kq * 4 + 1][srow] = packf2(bv0.z, bv0.w);
        Bs[kq * 4 + 2][srow] = packf2(bv1.x, bv1.y);
        Bs[kq * 4 + 3][srow] = packf2(bv1.z, bv1.w);
        __syncthreads();
        if (chunk < 3) {
            int o = (chunk + 1) * 8 + kq * 2;
            av0 = Arow[o]; av1 = Arow[o + 1];
            bv0 = Brow[o]; bv1 = Brow[o + 1];
        }
        #pragma unroll
        for (int k2 = 0; k2 < K2C; k2++) {
            ulonglong2 a2[4], b2[2];
            const ulonglong2* ap = reinterpret_cast<const ulonglong2*>(&As[k2][wm * 64]);
            #pragma unroll
            for (int h = 0; h < 4; h++) a2[h] = ap[mg + 8 * h];
            const ulonglong2* bp = reinterpret_cast<const ulonglong2*>(&Bs[k2][wn * 16]);
            #pragma unroll
            for (int v = 0; v < 2; v++) b2[v] = bp[ng + 4 * v];
            #pragma unroll
            for (int h = 0; h < 4; h++) {
                #pragma unroll
                for (int v = 0; v < 2; v++) {
                    acc[2*h+0][2*v+0] = fma2(a2[h].x, b2[v].x, acc[2*h+0][2*v+0]);
                    acc[2*h+0][2*v+1] = fma2(a2[h].x, b2[v].y, acc[2*h+0][2*v+1]);
                    acc[2*h+1][2*v+0] = fma2(a2[h].y, b2[v].x, acc[2*h+1][2*v+0]);
                    acc[2*h+1][2*v+1] = fma2(a2[h].y, b2[v].y, acc[2*h+1][2*v+1]);
                }
            }
        }
        __syncthreads();
    }

    // epilogue: dist2 + per-class hard mining
    float x2v[4]; int tj[4];
    #pragma unroll
    for (int v = 0; v < 2; v++)
        #pragma unroll
        for (int q = 0; q < 2; q++) {
            int n = nbase + wn * 16 + 2 * ng + 8 * v + q;
            x2v[2*v+q] = g_x2[n];
            tj[2*v+q]  = T[n];
        }
    #pragma unroll
    for (int h = 0; h < 4; h++) {
        #pragma unroll
        for (int p = 0; p < 2; p++) {
            int mloc = wm * 64 + 2 * mg + 16 * h + p;
            int cls  = cbase + mloc;
            float c2 = scm2[mloc];
            unsigned ep = 0u, en = 0xFFFFFFFFu;
            #pragma unroll
            for (int nj = 0; nj < 4; nj++) {
                float lo, hi; unpackf2(lo, hi, acc[2*h+p][nj]);
                float d2 = c2 + x2v[nj] - 2.f * (lo + hi);
                unsigned e = encf(d2);
                if (tj[nj] == cls) ep = ep > e ? ep : e;
                else               en = en < e ? en : e;
            }
            // reduce over the 4-lane ng group (lane bits 0-1)
            #pragma unroll
            for (int o = 1; o <= 2; o <<= 1) {
                unsigned tp = __shfl_xor_sync(0xffffffffu, ep, o);
                unsigned tn = __shfl_xor_sync(0xffffffffu, en, o);
                ep = ep > tp ? ep : tp;
                en = en < tn ? en : tn;
            }
            if (ng == 0) {
                atomicMax(&spos[mloc], ep);
                atomicMin(&sneg[mloc], en);
            }
        }
    }
    __syncthreads();
    if (tid < MT) {
        atomicMax(&g_pos[cbase + tid], spos[tid]);
        atomicMin(&g_neg[cbase + tid], sneg[tid]);
    }
}

// ---------------- K4: weighted final reduction -------------------------------
__global__ __launch_bounds__(1024) void k_final(float* __restrict__ out, int out_size) {
    __shared__ float sl[1024];
    __shared__ float sp[1024];
    int c = threadIdx.x;
    int cnt = g_count[c];
    float l = 0.f, p = 0.f;
    if (cnt > 0) {
        float pos = decf(g_pos[c]);
        float neg = decf(g_neg[c]);
        float d = pos - neg + MARGIN;
        l = (float)cnt * (d > 0.f ? d : 0.f);
        p = (float)cnt * (neg > pos ? 1.f : 0.f);
    }
    sl[c] = l;
    sp[c] = p;
    __syncthreads();
    for (int o = 512; o; o >>= 1) {
        if (c < o) { sl[c] += sl[c + o]; sp[c] += sp[c + o]; }
        __syncthreads();
    }
    if (c == 0) {
        out[0] = sl[0] / (float)NS;
        if (out_size > 1) out[1] = sp[0] / (float)NS;
    }
}

// ---------------- launch -----------------------------------------------------
extern "C" void kernel_launch(void* const* d_in, const int* in_sizes, int n_in,
                              void* d_out, int out_size) {
    const float* X = (const float*)d_in[0];
    const int*   T = (const int*)d_in[1];
    float*       O = (float*)d_out;

    k_pre<<<32 + NS / 32, 1024>>>(X, T);
    k_centers<<<NC, 128>>>(X);
    k_main<<<(NC / MT) * (NS / NT), 512>>>(X, T);
    k_final<<<1, 1024>>>(O, out_size);
}

// round 6
// speedup vs baseline: 3.5218x; 1.7228x over previous
#include <cuda_runtime.h>
#include <cuda_bf16.h>
#include <cstdint>

#define NS   8192
#define DIM  128
#define NC   1024
#define MARGIN 0.3f
#define LISTCAP 64
#define KK   384          // 3*DIM bf16 cols: A'=[hi|hi|lo], B'=[hi|lo|hi]

// ---------------- scratch (device globals) ----------------------------------
__device__ __align__(16) unsigned short g_A2[NC * KK];  // centers split bf16
__device__ __align__(16) unsigned short g_B2[NS * KK];  // samples split bf16
__device__ float    g_cm2[NC];
__device__ int      g_count[NC];
__device__ int      g_list[NC][LISTCAP];
__device__ float    g_x2[NS];
__device__ unsigned g_pos[NC];
__device__ unsigned g_neg[NC];

// order-preserving float <-> uint encoding
__device__ __forceinline__ unsigned encf(float f) {
    unsigned u = __float_as_uint(f);
    return (u & 0x80000000u) ? ~u : (u | 0x80000000u);
}
__device__ __forceinline__ float decf(unsigned e) {
    return (e & 0x80000000u) ? __uint_as_float(e ^ 0x80000000u)
                             : __uint_as_float(~e);
}
__device__ __forceinline__ uint32_t smem_u32(const void* p) {
    uint32_t a;
    asm("{ .reg .u64 t; cvta.to.shared.u64 t, %1; cvt.u32.u64 %0, t; }"
        : "=r"(a) : "l"(p));
    return a;
}
__device__ __forceinline__ void ldm_x4(uint32_t& r0, uint32_t& r1,
                                       uint32_t& r2, uint32_t& r3, uint32_t a) {
    asm volatile("ldmatrix.sync.aligned.m8n8.x4.shared.b16 {%0,%1,%2,%3}, [%4];"
                 : "=r"(r0), "=r"(r1), "=r"(r2), "=r"(r3) : "r"(a));
}
__device__ __forceinline__ void mma16816(float* c, const uint32_t* a,
                                         const uint32_t* b) {
    asm volatile("mma.sync.aligned.m16n8k16.row.col.f32.bf16.bf16.f32 "
                 "{%0,%1,%2,%3}, {%4,%5,%6,%7}, {%8,%9}, {%0,%1,%2,%3};"
                 : "+f"(c[0]), "+f"(c[1]), "+f"(c[2]), "+f"(c[3])
                 : "r"(a[0]), "r"(a[1]), "r"(a[2]), "r"(a[3]),
                   "r"(b[0]), "r"(b[1]));
}

// ---------------- K1: index lists + row norms + X split-convert --------------
__global__ __launch_bounds__(1024) void k_pre(const float* __restrict__ X,
                                              const int* __restrict__ T) {
    int tid = threadIdx.x, w = tid >> 5, lane = tid & 31;
    if (blockIdx.x < 32) {
        __shared__ int sT[NS];   // 32 KB
        for (int i = tid; i < NS; i += 1024) sT[i] = T[i];
        __syncthreads();
        int c = blockIdx.x * 32 + w;
        if (lane == 0) { g_pos[c] = 0u; g_neg[c] = 0xFFFFFFFFu; }
        int cnt = 0;
        for (int base = 0; base < NS; base += 32) {
            int t = sT[base + lane];
            unsigned bal = __ballot_sync(0xffffffffu, t == c);
            if (t == c) {
                int pos = cnt + __popc(bal & ((1u << lane) - 1u));
                if (pos < LISTCAP) g_list[c][pos] = base + lane;
            }
            cnt += __popc(bal);
        }
        if (lane == 0) g_count[c] = cnt;
    } else {
        int row = (blockIdx.x - 32) * 32 + w;
        const float4* rp = reinterpret_cast<const float4*>(X + (size_t)row * DIM);
        float4 v = rp[lane];
        float s = v.x * v.x + v.y * v.y + v.z * v.z + v.w * v.w;
        #pragma unroll
        for (int o = 16; o; o >>= 1) s += __shfl_xor_sync(0xffffffffu, s, o);
        if (lane == 0) g_x2[row] = s;
        __nv_bfloat16 h0 = __float2bfloat16(v.x), h1 = __float2bfloat16(v.y);
        __nv_bfloat16 h2 = __float2bfloat16(v.z), h3 = __float2bfloat16(v.w);
        __nv_bfloat16 l0 = __float2bfloat16(v.x - __bfloat162float(h0));
        __nv_bfloat16 l1 = __float2bfloat16(v.y - __bfloat162float(h1));
        __nv_bfloat16 l2 = __float2bfloat16(v.z - __bfloat162float(h2));
        __nv_bfloat16 l3 = __float2bfloat16(v.w - __bfloat162float(h3));
        ushort4 hv, lv;
        hv.x = __bfloat16_as_ushort(h0); hv.y = __bfloat16_as_ushort(h1);
        hv.z = __bfloat16_as_ushort(h2); hv.w = __bfloat16_as_ushort(h3);
        lv.x = __bfloat16_as_ushort(l0); lv.y = __bfloat16_as_ushort(l1);
        lv.z = __bfloat16_as_ushort(l2); lv.w = __bfloat16_as_ushort(l3);
        unsigned short* B2 = g_B2 + (size_t)row * KK;
        *reinterpret_cast<ushort4*>(B2 + lane * 4)       = hv;  // blk0: hi
        *reinterpret_cast<ushort4*>(B2 + 128 + lane * 4) = lv;  // blk1: lo
        *reinterpret_cast<ushort4*>(B2 + 256 + lane * 4) = hv;  // blk2: hi
    }
}

// ---------------- K2: class means + split-convert + ||m||^2 ------------------
__global__ __launch_bounds__(128) void k_centers(const float* __restrict__ X) {
    int c = blockIdx.x, tid = threadIdx.x;
    int cnt = g_count[c];
    int cl = cnt > LISTCAP ? LISTCAP : cnt;
    float s = 0.f;
    int i = 0;
    for (; i + 4 <= cl; i += 4) {
        int i0 = g_list[c][i], i1 = g_list[c][i+1], i2 = g_list[c][i+2], i3 = g_list[c][i+3];
        s += X[(size_t)i0 * DIM + tid];
        s += X[(size_t)i1 * DIM + tid];
        s += X[(size_t)i2 * DIM + tid];
        s += X[(size_t)i3 * DIM + tid];
    }
    for (; i < cl; i++) s += X[(size_t)g_list[c][i] * DIM + tid];
    float m = (cnt > 0) ? s / (float)cnt : 0.f;
    __nv_bfloat16 hm = __float2bfloat16(m);
    __nv_bfloat16 lm = __float2bfloat16(m - __bfloat162float(hm));
    unsigned short hu = __bfloat16_as_ushort(hm), lu = __bfloat16_as_ushort(lm);
    g_A2[(size_t)c * KK + tid]       = hu;  // blk0: hi (pairs B hi)
    g_A2[(size_t)c * KK + 128 + tid] = hu;  // blk1: hi (pairs B lo)
    g_A2[(size_t)c * KK + 256 + tid] = lu;  // blk2: lo (pairs B hi)
    float q = m * m;
    #pragma unroll
    for (int o = 16; o; o >>= 1) q += __shfl_xor_sync(0xffffffffu, q, o);
    __shared__ float r[4];
    if ((tid & 31) == 0) r[tid >> 5] = q;
    __syncthreads();
    if (tid == 0) g_cm2[c] = r[0] + r[1] + r[2] + r[3];
}

// ---------------- K3: bf16 HMMA GEMM (mma.sync) + hard mining ----------------
// 512 CTAs (8 class-tiles x 64 n-tiles), 256 thr = 8 warps (2m x 4n),
// warp tile 64m x 32n. K'=384 staged in 6 chunks of 64 bf16.
// Smem rows padded to 72 bf16 (144 B): ldmatrix rows land on distinct bank
// quads; quarter-warp STS.128 conflict-free.
#define SROW 72
__global__ __launch_bounds__(256, 2) void k_mma(const int* __restrict__ T) {
    __shared__ float    scm2[128], sx2[128];
    __shared__ int      sTl[128];
    __shared__ unsigned spos[128], sneg[128];
    __shared__ __align__(16) unsigned short sA[128 * SROW];  // 18 KB
    __shared__ __align__(16) unsigned short sB[128 * SROW];  // 18 KB

    int tid = threadIdx.x, lane = tid & 31, w = tid >> 5;
    int wm = w & 1, wn = w >> 1;            // warps 2 x 4
    int cbase = (blockIdx.x & 7) * 128;
    int nbase = (blockIdx.x >> 3) * 128;

    if (tid < 128) {
        scm2[tid] = g_cm2[cbase + tid];
        sx2[tid]  = g_x2[nbase + tid];
        sTl[tid]  = T[nbase + tid];
        spos[tid] = 0u;
        sneg[tid] = 0xFFFFFFFFu;
    }

    float acc[4][4][4];
    #pragma unroll
    for (int mt = 0; mt < 4; mt++)
        #pragma unroll
        for (int nt = 0; nt < 4; nt++)
            #pragma unroll
            for (int k = 0; k < 4; k++) acc[mt][nt][k] = 0.f;

    uint32_t sAu = smem_u32(sA), sBu = smem_u32(sB);
    const uint4* Ag = reinterpret_cast<const uint4*>(g_A2);
    const uint4* Bg = reinterpret_cast<const uint4*>(g_B2);

    // fragment addresses (fixed per lane; +chunk col advances)
    int am = wm * 64 + (lane & 15);
    uint32_t aAbase = sAu + (am * SROW + (lane >> 4) * 8) * 2;
    int bn = wn * 32 + (lane >> 4) * 8 + (lane & 7);
    uint32_t aBbase = sBu + (bn * SROW + ((lane >> 3) & 1) * 8) * 2;

    for (int c = 0; c < 6; c++) {
        #pragma unroll
        for (int i = tid; i < 1024; i += 256) {
            int r = i >> 3, q = i & 7;
            reinterpret_cast<uint4*>(sA)[r * 9 + q] =
                Ag[(size_t)(cbase + r) * 48 + c * 8 + q];
            reinterpret_cast<uint4*>(sB)[r * 9 + q] =
                Bg[(size_t)(nbase + r) * 48 + c * 8 + q];
        }
        __syncthreads();
        #pragma unroll
        for (int kk = 0; kk < 4; kk++) {
            uint32_t b[4][2];
            #pragma unroll
            for (int np = 0; np < 2; np++) {   // ntile pairs (0,1),(2,3)
                uint32_t addr = aBbase + (np * 16 * SROW + kk * 16) * 2;
                ldm_x4(b[np*2][0], b[np*2][1], b[np*2+1][0], b[np*2+1][1], addr);
            }
            #pragma unroll
            for (int mt = 0; mt < 4; mt++) {
                uint32_t a[4];
                uint32_t addr = aAbase + (mt * 16 * SROW + kk * 16) * 2;
                ldm_x4(a[0], a[1], a[2], a[3], addr);
                #pragma unroll
                for (int nt = 0; nt < 4; nt++)
                    mma16816(acc[mt][nt], a, b[nt]);
            }
        }
        __syncthreads();
    }

    // epilogue: fragment layout c0:(g,2q) c1:(g,2q+1) c2:(g+8,..) c3
    #pragma unroll
    for (int mt = 0; mt < 4; mt++) {
        #pragma unroll
        for (int h = 0; h < 2; h++) {
            int mloc = wm * 64 + mt * 16 + (lane >> 2) + h * 8;
            int cls  = cbase + mloc;
            float c2 = scm2[mloc];
            unsigned ep = 0u, en = 0xFFFFFFFFu;
            #pragma unroll
            for (int nt = 0; nt < 4; nt++) {
                #pragma unroll
                for (int q = 0; q < 2; q++) {
                    int nloc = wn * 32 + nt * 8 + (lane & 3) * 2 + q;
                    float d2 = c2 + sx2[nloc] - 2.f * acc[mt][nt][h * 2 + q];
                    unsigned e = encf(d2);
                    if (sTl[nloc] == cls) ep = ep > e ? ep : e;
                    else                  en = en < e ? en : e;
                }
            }
            #pragma unroll
            for (int o = 1; o <= 2; o <<= 1) {
                unsigned tp = __shfl_xor_sync(0xffffffffu, ep, o);
                unsigned tn = __shfl_xor_sync(0xffffffffu, en, o);
                ep = ep > tp ? ep : tp;
                en = en < tn ? en : tn;
            }
            if ((lane & 3) == 0) {
                atomicMax(&spos[mloc], ep);
                atomicMin(&sneg[mloc], en);
            }
        }
    }
    __syncthreads();
    if (tid < 128) {
        atomicMax(&g_pos[cbase + tid], spos[tid]);
        atomicMin(&g_neg[cbase + tid], sneg[tid]);
    }
}

// ---------------- K4: weighted final reduction -------------------------------
__global__ __launch_bounds__(256) void k_final(float* __restrict__ out, int out_size) {
    int tid = threadIdx.x;
    float l = 0.f, p = 0.f;
    for (int c = tid; c < NC; c += 256) {
        int cnt = g_count[c];
        if (cnt > 0) {
            float pos = decf(g_pos[c]);
            float neg = decf(g_neg[c]);
            float d = pos - neg + MARGIN;
            l += (float)cnt * (d > 0.f ? d : 0.f);
            p += (float)cnt * (neg > pos ? 1.f : 0.f);
        }
    }
    #pragma unroll
    for (int o = 16; o; o >>= 1) {
        l += __shfl_xor_sync(0xffffffffu, l, o);
        p += __shfl_xor_sync(0xffffffffu, p, o);
    }
    __shared__ float rl[8], rp[8];
    if ((tid & 31) == 0) { rl[tid >> 5] = l; rp[tid >> 5] = p; }
    __syncthreads();
    if (tid == 0) {
        float L = 0.f, P = 0.f;
        #pragma unroll
        for (int i = 0; i < 8; i++) { L += rl[i]; P += rp[i]; }
        out[0] = L / (float)NS;
        if (out_size > 1) out[1] = P / (float)NS;
    }
}

// ---------------- launch -----------------------------------------------------
extern "C" void kernel_launch(void* const* d_in, const int* in_sizes, int n_in,
                              void* d_out, int out_size) {
    const float* X = (const float*)d_in[0];
    const int*   T = (const int*)d_in[1];
    float*       O = (float*)d_out;

    k_pre<<<32 + NS / 32, 1024>>>(X, T);
    k_centers<<<NC, 128>>>(X);
    k_mma<<<512, 256>>>(T);
    k_final<<<1, 256>>>(O, out_size);
}

// round 7
// speedup vs baseline: 3.5240x; 1.0006x over previous
#include <cuda_runtime.h>
#include <cuda_bf16.h>
#include <cstdint>

#define NS   8192
#define DIM  128
#define NC   1024
#define MARGIN 0.3f
#define LISTCAP 64
#define KK   384          // 3*DIM bf16 cols: A'=[hi|hi|lo], B'=[hi|lo|hi]

// ---------------- scratch (device globals) ----------------------------------
__device__ __align__(16) unsigned short g_A2[NC * KK];  // centers split bf16
__device__ __align__(16) unsigned short g_B2[NS * KK];  // samples split bf16
__device__ float    g_cm2[NC];
__device__ int      g_count[NC];
__device__ int      g_list[NC][LISTCAP];
__device__ float    g_x2[NS];
__device__ unsigned g_pos[NC];
__device__ unsigned g_neg[NC];
__device__ unsigned g_done;

// order-preserving float <-> uint encoding
__device__ __forceinline__ unsigned encf(float f) {
    unsigned u = __float_as_uint(f);
    return (u & 0x80000000u) ? ~u : (u | 0x80000000u);
}
__device__ __forceinline__ float decf(unsigned e) {
    return (e & 0x80000000u) ? __uint_as_float(e ^ 0x80000000u)
                             : __uint_as_float(~e);
}
__device__ __forceinline__ uint32_t smem_u32(const void* p) {
    uint32_t a;
    asm("{ .reg .u64 t; cvta.to.shared.u64 t, %1; cvt.u32.u64 %0, t; }"
        : "=r"(a) : "l"(p));
    return a;
}
__device__ __forceinline__ void ldm_x4(uint32_t& r0, uint32_t& r1,
                                       uint32_t& r2, uint32_t& r3, uint32_t a) {
    asm volatile("ldmatrix.sync.aligned.m8n8.x4.shared.b16 {%0,%1,%2,%3}, [%4];"
                 : "=r"(r0), "=r"(r1), "=r"(r2), "=r"(r3) : "r"(a));
}
__device__ __forceinline__ void mma16816(float* c, const uint32_t* a,
                                         const uint32_t* b) {
    asm volatile("mma.sync.aligned.m16n8k16.row.col.f32.bf16.bf16.f32 "
                 "{%0,%1,%2,%3}, {%4,%5,%6,%7}, {%8,%9}, {%0,%1,%2,%3};"
                 : "+f"(c[0]), "+f"(c[1]), "+f"(c[2]), "+f"(c[3])
                 : "r"(a[0]), "r"(a[1]), "r"(a[2]), "r"(a[3]),
                   "r"(b[0]), "r"(b[1]));
}
__device__ __forceinline__ void cpasync16(uint32_t saddr, const void* gaddr) {
    asm volatile("cp.async.cg.shared.global [%0], [%1], 16;"
                 :: "r"(saddr), "l"(gaddr));
}
#define CP_COMMIT() asm volatile("cp.async.commit_group;" ::: "memory")
#define CP_WAIT0()  asm volatile("cp.async.wait_group 0;" ::: "memory")

// ---------------- K1: index lists + row norms + X split-convert --------------
__global__ __launch_bounds__(1024) void k_pre(const float* __restrict__ X,
                                              const int* __restrict__ T) {
    int tid = threadIdx.x, w = tid >> 5, lane = tid & 31;
    if (blockIdx.x == 0 && tid == 0) g_done = 0u;
    if (blockIdx.x < 32) {
        __shared__ int sT[NS];   // 32 KB
        for (int i = tid; i < NS; i += 1024) sT[i] = T[i];
        __syncthreads();
        int c = blockIdx.x * 32 + w;
        if (lane == 0) { g_pos[c] = 0u; g_neg[c] = 0xFFFFFFFFu; }
        int cnt = 0;
        for (int base = 0; base < NS; base += 32) {
            int t = sT[base + lane];
            unsigned bal = __ballot_sync(0xffffffffu, t == c);
            if (t == c) {
                int pos = cnt + __popc(bal & ((1u << lane) - 1u));
                if (pos < LISTCAP) g_list[c][pos] = base + lane;
            }
            cnt += __popc(bal);
        }
        if (lane == 0) g_count[c] = cnt;
    } else {
        int row = (blockIdx.x - 32) * 32 + w;
        const float4* rp = reinterpret_cast<const float4*>(X + (size_t)row * DIM);
        float4 v = rp[lane];
        float s = v.x * v.x + v.y * v.y + v.z * v.z + v.w * v.w;
        #pragma unroll
        for (int o = 16; o; o >>= 1) s += __shfl_xor_sync(0xffffffffu, s, o);
        if (lane == 0) g_x2[row] = s;
        __nv_bfloat16 h0 = __float2bfloat16(v.x), h1 = __float2bfloat16(v.y);
        __nv_bfloat16 h2 = __float2bfloat16(v.z), h3 = __float2bfloat16(v.w);
        __nv_bfloat16 l0 = __float2bfloat16(v.x - __bfloat162float(h0));
        __nv_bfloat16 l1 = __float2bfloat16(v.y - __bfloat162float(h1));
        __nv_bfloat16 l2 = __float2bfloat16(v.z - __bfloat162float(h2));
        __nv_bfloat16 l3 = __float2bfloat16(v.w - __bfloat162float(h3));
        ushort4 hv, lv;
        hv.x = __bfloat16_as_ushort(h0); hv.y = __bfloat16_as_ushort(h1);
        hv.z = __bfloat16_as_ushort(h2); hv.w = __bfloat16_as_ushort(h3);
        lv.x = __bfloat16_as_ushort(l0); lv.y = __bfloat16_as_ushort(l1);
        lv.z = __bfloat16_as_ushort(l2); lv.w = __bfloat16_as_ushort(l3);
        unsigned short* B2 = g_B2 + (size_t)row * KK;
        *reinterpret_cast<ushort4*>(B2 + lane * 4)       = hv;  // blk0: hi
        *reinterpret_cast<ushort4*>(B2 + 128 + lane * 4) = lv;  // blk1: lo
        *reinterpret_cast<ushort4*>(B2 + 256 + lane * 4) = hv;  // blk2: hi
    }
}

// ---------------- K2: class means + split-convert + ||m||^2 ------------------
__global__ __launch_bounds__(128) void k_centers(const float* __restrict__ X) {
    int c = blockIdx.x, tid = threadIdx.x;
    int cnt = g_count[c];
    int cl = cnt > LISTCAP ? LISTCAP : cnt;
    float s = 0.f;
    int i = 0;
    for (; i + 4 <= cl; i += 4) {
        int i0 = g_list[c][i], i1 = g_list[c][i+1], i2 = g_list[c][i+2], i3 = g_list[c][i+3];
        s += X[(size_t)i0 * DIM + tid];
        s += X[(size_t)i1 * DIM + tid];
        s += X[(size_t)i2 * DIM + tid];
        s += X[(size_t)i3 * DIM + tid];
    }
    for (; i < cl; i++) s += X[(size_t)g_list[c][i] * DIM + tid];
    float m = (cnt > 0) ? s / (float)cnt : 0.f;
    __nv_bfloat16 hm = __float2bfloat16(m);
    __nv_bfloat16 lm = __float2bfloat16(m - __bfloat162float(hm));
    unsigned short hu = __bfloat16_as_ushort(hm), lu = __bfloat16_as_ushort(lm);
    g_A2[(size_t)c * KK + tid]       = hu;
    g_A2[(size_t)c * KK + 128 + tid] = hu;
    g_A2[(size_t)c * KK + 256 + tid] = lu;
    float q = m * m;
    #pragma unroll
    for (int o = 16; o; o >>= 1) q += __shfl_xor_sync(0xffffffffu, q, o);
    __shared__ float r[4];
    if ((tid & 31) == 0) r[tid >> 5] = q;
    __syncthreads();
    if (tid == 0) g_cm2[c] = r[0] + r[1] + r[2] + r[3];
}

// ---------------- K3: bf16 HMMA GEMM + hard mining + fused final -------------
// 512 CTAs (8 class-tiles x 64 n-tiles), 256 thr = 8 warps (2m x 4n),
// warp tile 64m x 32n. K'=384 in 6 chunks of 64 bf16, double-buffered via
// cp.async (dynamic smem, 2 x 36864 B). Last CTA does the final reduction.
#define SROW 72
#define TILEB 18432            // 128*72*2
#define STAGEB (TILEB * 2)     // A + B per stage
#define GRID_MMA 512
__global__ __launch_bounds__(256, 2) void k_mma(const int* __restrict__ T,
                                                float* __restrict__ out,
                                                int out_size) {
    extern __shared__ __align__(16) char dyn[];
    __shared__ float    scm2[128], sx2[128];
    __shared__ int      sTl[128];
    __shared__ unsigned spos[128], sneg[128];
    __shared__ unsigned is_last;

    int tid = threadIdx.x, lane = tid & 31, w = tid >> 5;
    int wm = w & 1, wn = w >> 1;            // warps 2 x 4
    int cbase = (blockIdx.x & 7) * 128;
    int nbase = (blockIdx.x >> 3) * 128;

    if (tid < 128) {
        scm2[tid] = g_cm2[cbase + tid];
        sx2[tid]  = g_x2[nbase + tid];
        sTl[tid]  = T[nbase + tid];
        spos[tid] = 0u;
        sneg[tid] = 0xFFFFFFFFu;
    }

    float acc[4][4][4];
    #pragma unroll
    for (int mt = 0; mt < 4; mt++)
        #pragma unroll
        for (int nt = 0; nt < 4; nt++)
            #pragma unroll
            for (int k = 0; k < 4; k++) acc[mt][nt][k] = 0.f;

    uint32_t dynu = smem_u32(dyn);
    const uint4* Ag = reinterpret_cast<const uint4*>(g_A2);
    const uint4* Bg = reinterpret_cast<const uint4*>(g_B2);

    // staging indices: 4 uint4 per thread per tile
    int ir[4], iq[4];
    #pragma unroll
    for (int k = 0; k < 4; k++) { int i = tid + k * 256; ir[k] = i >> 3; iq[k] = i & 7; }

    // fragment base offsets (within a stage buffer)
    int am = wm * 64 + (lane & 15);
    uint32_t offA = (uint32_t)(am * SROW + (lane >> 4) * 8) * 2;
    int bn = wn * 32 + (lane >> 4) * 8 + (lane & 7);
    uint32_t offB = (uint32_t)TILEB + (uint32_t)(bn * SROW + ((lane >> 3) & 1) * 8) * 2;

    // prologue: stage chunk 0 into buffer 0
    #pragma unroll
    for (int k = 0; k < 4; k++) {
        uint32_t sa = dynu + (uint32_t)(ir[k] * 9 + iq[k]) * 16;
        cpasync16(sa,          Ag + (size_t)(cbase + ir[k]) * 48 + iq[k]);
        cpasync16(sa + TILEB,  Bg + (size_t)(nbase + ir[k]) * 48 + iq[k]);
    }
    CP_COMMIT();

    for (int c = 0; c < 6; c++) {
        CP_WAIT0();
        __syncthreads();
        uint32_t cur = dynu + (uint32_t)(c & 1) * STAGEB;
        if (c < 5) {
            uint32_t nxt = dynu + (uint32_t)((c + 1) & 1) * STAGEB;
            #pragma unroll
            for (int k = 0; k < 4; k++) {
                uint32_t sa = nxt + (uint32_t)(ir[k] * 9 + iq[k]) * 16;
                cpasync16(sa,         Ag + (size_t)(cbase + ir[k]) * 48 + (c + 1) * 8 + iq[k]);
                cpasync16(sa + TILEB, Bg + (size_t)(nbase + ir[k]) * 48 + (c + 1) * 8 + iq[k]);
            }
            CP_COMMIT();
        }
        #pragma unroll
        for (int kk = 0; kk < 4; kk++) {
            uint32_t b[4][2];
            #pragma unroll
            for (int np = 0; np < 2; np++) {
                uint32_t addr = cur + offB + (uint32_t)(np * 16 * SROW + kk * 16) * 2;
                ldm_x4(b[np*2][0], b[np*2][1], b[np*2+1][0], b[np*2+1][1], addr);
            }
            #pragma unroll
            for (int mt = 0; mt < 4; mt++) {
                uint32_t a[4];
                uint32_t addr = cur + offA + (uint32_t)(mt * 16 * SROW + kk * 16) * 2;
                ldm_x4(a[0], a[1], a[2], a[3], addr);
                #pragma unroll
                for (int nt = 0; nt < 4; nt++)
                    mma16816(acc[mt][nt], a, b[nt]);
            }
        }
        if (c < 5) __syncthreads();   // compute done before next overwrite wave
    }

    // epilogue: fragment (2 rows x 8 cols per thread per mt) hard mining
    #pragma unroll
    for (int mt = 0; mt < 4; mt++) {
        #pragma unroll
        for (int h = 0; h < 2; h++) {
            int mloc = wm * 64 + mt * 16 + (lane >> 2) + h * 8;
            int cls  = cbase + mloc;
            float c2 = scm2[mloc];
            unsigned ep = 0u, en = 0xFFFFFFFFu;
            #pragma unroll
            for (int nt = 0; nt < 4; nt++) {
                #pragma unroll
                for (int q = 0; q < 2; q++) {
                    int nloc = wn * 32 + nt * 8 + (lane & 3) * 2 + q;
                    float d2 = c2 + sx2[nloc] - 2.f * acc[mt][nt][h * 2 + q];
                    unsigned e = encf(d2);
                    if (sTl[nloc] == cls) ep = ep > e ? ep : e;
                    else                  en = en < e ? en : e;
                }
            }
            #pragma unroll
            for (int o = 1; o <= 2; o <<= 1) {
                unsigned tp = __shfl_xor_sync(0xffffffffu, ep, o);
                unsigned tn = __shfl_xor_sync(0xffffffffu, en, o);
                ep = ep > tp ? ep : tp;
                en = en < tn ? en : tn;
            }
            if ((lane & 3) == 0) {
                atomicMax(&spos[mloc], ep);
                atomicMin(&sneg[mloc], en);
            }
        }
    }
    __syncthreads();
    if (tid < 128) {
        atomicMax(&g_pos[cbase + tid], spos[tid]);
        atomicMin(&g_neg[cbase + tid], sneg[tid]);
    }

    // ---- fused final reduction (last CTA) ----
    __threadfence();
    __syncthreads();
    if (tid == 0)
        is_last = (atomicAdd(&g_done, 1u) == (unsigned)(GRID_MMA - 1)) ? 1u : 0u;
    __syncthreads();
    if (is_last) {
        float l = 0.f, p = 0.f;
        for (int c = tid; c < NC; c += 256) {
            int cnt = g_count[c];
            if (cnt > 0) {
                float pos = decf(g_pos[c]);
                float neg = decf(g_neg[c]);
                float d = pos - neg + MARGIN;
                l += (float)cnt * (d > 0.f ? d : 0.f);
                p += (float)cnt * (neg > pos ? 1.f : 0.f);
            }
        }
        #pragma unroll
        for (int o = 16; o; o >>= 1) {
            l += __shfl_xor_sync(0xffffffffu, l, o);
            p += __shfl_xor_sync(0xffffffffu, p, o);
        }
        __shared__ float rl[8], rp[8];
        if ((tid & 31) == 0) { rl[tid >> 5] = l; rp[tid >> 5] = p; }
        __syncthreads();
        if (tid == 0) {
            float L = 0.f, P = 0.f;
            #pragma unroll
            for (int i = 0; i < 8; i++) { L += rl[i]; P += rp[i]; }
            out[0] = L / (float)NS;
            if (out_size > 1) out[1] = P / (float)NS;
            g_done = 0u;
        }
    }
}

// ---------------- launch -----------------------------------------------------
extern "C" void kernel_launch(void* const* d_in, const int* in_sizes, int n_in,
                              void* d_out, int out_size) {
    const float* X = (const float*)d_in[0];
    const int*   T = (const int*)d_in[1];
    float*       O = (float*)d_out;

    cudaFuncSetAttribute(k_mma, cudaFuncAttributeMaxDynamicSharedMemorySize,
                         STAGEB * 2);

    k_pre<<<32 + NS / 32, 1024>>>(X, T);
    k_centers<<<NC, 128>>>(X);
    k_mma<<<GRID_MMA, 256, STAGEB * 2>>>(T, O, out_size);
}